// round 17
// baseline (speedup 1.0000x reference)
#include <cuda_runtime.h>

#define NBATCH 256
#define NTOK   4096
#define NCH    8
#define SCALEF 0.125f
#define EPSA   1e-8f

// ---------------- global scratch ----------------
__device__ float g_slots[NBATCH * 512];
__device__ float g_prior[NBATCH * 1024];
__device__ float g_kl[NBATCH * 8];
__device__ float g_qg[NBATCH * 512];
__device__ float g_qgs[NBATCH * 8];
__device__ float g_qb[NBATCH * 8];
__device__ float g_pA[NBATCH * NCH * 8 * 64];
__device__ float g_pW[NBATCH * NCH * 8];
__device__ float g_pT[NBATCH * NCH * 8];

__device__ __forceinline__ float sigmoidf_(float x) { return 1.0f / (1.0f + expf(-x)); }
__device__ __forceinline__ float dot4(float4 a, float4 b) {
    return a.x * b.x + a.y * b.y + a.z * b.z + a.w * b.w;
}

// ---- TMA bulk 1D helpers ----
__device__ __forceinline__ void mbar_init(unsigned mbar, unsigned count) {
    asm volatile("mbarrier.init.shared.b64 [%0], %1;" :: "r"(mbar), "r"(count) : "memory");
}
__device__ __forceinline__ void mbar_expect_tx(unsigned mbar, unsigned bytes) {
    asm volatile("mbarrier.arrive.expect_tx.shared.b64 _, [%0], %1;" :: "r"(mbar), "r"(bytes) : "memory");
}
__device__ __forceinline__ void tma_bulk_g2s(unsigned smem_dst, const void* gsrc, unsigned bytes, unsigned mbar) {
    asm volatile(
        "cp.async.bulk.shared::cta.global.mbarrier::complete_tx::bytes [%0], [%1], %2, [%3];"
        :: "r"(smem_dst), "l"(gsrc), "r"(bytes), "r"(mbar) : "memory");
}
__device__ __forceinline__ void mbar_wait(unsigned mbar, unsigned phase) {
    asm volatile(
        "{\n\t"
        ".reg .pred P;\n\t"
        "WAITLOOP_%=:\n\t"
        "mbarrier.try_wait.parity.shared.b64 P, [%0], %1;\n\t"
        "@!P bra WAITLOOP_%=;\n\t"
        "}"
        :: "r"(mbar), "r"(phase) : "memory");
}

// =======================================================================
// ATTENTION: 2048 blocks (batch x 8 chunks of 512 tokens) x 256 threads
// TMA bulk double-buffered tiles, unpadded [64][64] layout.
// =======================================================================
#define AQ_QG   0           // [8][68] padded (17 float4 per slot)
#define AQ_QGS  544
#define AQ_QB   552
#define AQ_MB   560         // 2 mbarriers
#define AQ_WT2  564         // [64 tokens][8 slots] w'
#define AQ_WR   1076        // [64][8]
#define AQ_TR   1588        // [64][8]
#define AQ_KT0  2112        // [64][64] floats, 128B-aligned
#define AQ_KT1  6208
#define AQ_RED  AQ_KT0      // epilogue alias (last tile uses KT1)
#define AQ_TOT  10304
#define AQ_BYTES (AQ_TOT * 4)
#define TILE_BYTES 16384u

__global__ __launch_bounds__(256, 4) void attn_kernel(const float* __restrict__ inputs)
{
    extern __shared__ float sm[];
    const int blk = blockIdx.x;
    const int b = blk >> 3, chunk = blk & 7;
    const int t = threadIdx.x;
    const unsigned smem_base = (unsigned)__cvta_generic_to_shared(sm);
    const unsigned mb0 = smem_base + AQ_MB * 4;
    const unsigned mb1 = mb0 + 8;

    for (int e = t; e < 512; e += 256)
        sm[AQ_QG + (e >> 6) * 68 + (e & 63)] = g_qg[b * 512 + e];
    if (t < 8) { sm[AQ_QGS + t] = g_qgs[b * 8 + t]; sm[AQ_QB + t] = g_qb[b * 8 + t]; }

    const float* base = inputs + ((long)b * NTOK + chunk * 512) * 64;

    if (t == 0) {
        mbar_init(mb0, 1);
        mbar_init(mb1, 1);
    }
    __syncthreads();
    asm volatile("fence.proxy.async.shared::cta;" ::: "memory");
    if (t == 0) {
        mbar_expect_tx(mb0, TILE_BYTES);
        tma_bulk_g2s(smem_base + AQ_KT0 * 4, base, TILE_BYTES, mb0);
        mbar_expect_tx(mb1, TILE_BYTES);
        tma_bulk_g2s(smem_base + AQ_KT1 * 4, base + 64 * 64, TILE_BYTES, mb1);
    }

    // dots roles
    const int j = t >> 2, seg = t & 3;
    const int i0 = seg * 2;
    const int rot = (2 * (j & 1) + (seg >> 1)) & 3;
    // accum roles
    const int a_d8 = t & 7, a_p = (t >> 3) & 3, a_jg = t >> 5;
    float4 a00 = {0,0,0,0}, a01 = {0,0,0,0}, a10 = {0,0,0,0}, a11 = {0,0,0,0};
    float Wp0 = 0.f, Wp1 = 0.f, Tp0 = 0.f, Tp1 = 0.f;
    // loop-invariant scalars
    float qgs0, qgs1, qb0, qb1;
    __syncthreads();
    qgs0 = sm[AQ_QGS + i0]; qgs1 = sm[AQ_QGS + i0 + 1];
    qb0  = sm[AQ_QB + i0];  qb1  = sm[AQ_QB + i0 + 1];

    for (int tt = 0; tt < 8; ++tt) {
        const int buf = tt & 1;
        float4* kt4 = (float4*)(sm + (buf ? AQ_KT1 : AQ_KT0));
        mbar_wait(buf ? mb1 : mb0, (tt >> 1) & 1);
        __syncthreads();

        // ---- dots (LN folded) ----
        {
            float s = 0.f, ss = 0.f;
            float dp[8];
            #pragma unroll
            for (int i = 0; i < 8; ++i) dp[i] = 0.f;
            const float4* xrow = kt4 + j * 16 + seg * 4;
            const float4* qg4  = (const float4*)(sm + AQ_QG);
            #pragma unroll
            for (int c = 0; c < 4; ++c) {
                int cc = (c + rot) & 3;
                float4 x4 = xrow[cc];
                s  += (x4.x + x4.y) + (x4.z + x4.w);
                ss += x4.x * x4.x + x4.y * x4.y + x4.z * x4.z + x4.w * x4.w;
                #pragma unroll
                for (int i = 0; i < 8; ++i)
                    dp[i] += dot4(x4, qg4[i * 17 + seg * 4 + cc]);
            }
            s  += __shfl_xor_sync(~0u, s, 1);  s  += __shfl_xor_sync(~0u, s, 2);
            ss += __shfl_xor_sync(~0u, ss, 1); ss += __shfl_xor_sync(~0u, ss, 2);
            #pragma unroll
            for (int i = 0; i < 8; ++i) {
                dp[i] += __shfl_xor_sync(~0u, dp[i], 1);
                dp[i] += __shfl_xor_sync(~0u, dp[i], 2);
            }
            float m = s * (1.f / 64.f);
            float var = ss * (1.f / 64.f) - m * m;
            float rstd = rsqrtf(var + 1e-5f);
            float mr = m * rstd;
            float dv0 = rstd * dp[i0]     - mr * qgs0 + qb0;
            float dv1 = rstd * dp[i0 + 1] - mr * qgs1 + qb1;
            float mx = fmaxf(dv0, dv1);
            mx = fmaxf(mx, __shfl_xor_sync(~0u, mx, 1));
            mx = fmaxf(mx, __shfl_xor_sync(~0u, mx, 2));
            float e0 = __expf(dv0 - mx), e1 = __expf(dv1 - mx);
            float sum = e0 + e1;
            sum += __shfl_xor_sync(~0u, sum, 1);
            sum += __shfl_xor_sync(~0u, sum, 2);
            float inv = 1.0f / sum;
            float w0 = e0 * inv + EPSA, w1 = e1 * inv + EPSA;
            float wp0 = w0 * rstd, wp1 = w1 * rstd;
            ((float2*)(sm + AQ_WT2))[j * 4 + seg] = make_float2(wp0, wp1);
            Wp0 += w0; Wp1 += w1;
            Tp0 += wp0 * m; Tp1 += wp1 * m;
        }
        __syncthreads();

        // ---- accumulate: 2 slots per thread ----
        #pragma unroll
        for (int k = 0; k < 8; ++k) {
            int jj = a_jg * 8 + k;
            float2 wp = ((float2*)(sm + AQ_WT2))[jj * 4 + a_p];
            float4 x0 = kt4[jj * 16 + a_d8];
            float4 x1 = kt4[jj * 16 + a_d8 + 8];
            a00.x += wp.x * x0.x; a00.y += wp.x * x0.y; a00.z += wp.x * x0.z; a00.w += wp.x * x0.w;
            a01.x += wp.x * x1.x; a01.y += wp.x * x1.y; a01.z += wp.x * x1.z; a01.w += wp.x * x1.w;
            a10.x += wp.y * x0.x; a10.y += wp.y * x0.y; a10.z += wp.y * x0.z; a10.w += wp.y * x0.w;
            a11.x += wp.y * x1.x; a11.y += wp.y * x1.y; a11.z += wp.y * x1.z; a11.w += wp.y * x1.w;
        }
        __syncthreads();

        // ---- refill this buffer with tile tt+2 ----
        if (tt < 6 && t == 0) {
            unsigned mb = buf ? mb1 : mb0;
            mbar_expect_tx(mb, TILE_BYTES);
            tma_bulk_g2s(smem_base + (buf ? AQ_KT1 : AQ_KT0) * 4,
                         base + (unsigned)(tt + 2) * 64 * 64, TILE_BYTES, mb);
        }
    }

    // ---- epilogue (RED aliases KT0; last tile used KT1) ----
    {
        float4* red = (float4*)(sm + AQ_RED);
        red[t * 4 + 0] = a00; red[t * 4 + 1] = a01;
        red[t * 4 + 2] = a10; red[t * 4 + 3] = a11;
        sm[AQ_WR + j * 8 + i0]     = Wp0;
        sm[AQ_WR + j * 8 + i0 + 1] = Wp1;
        sm[AQ_TR + j * 8 + i0]     = Tp0;
        sm[AQ_TR + j * 8 + i0 + 1] = Tp1;
    }
    __syncthreads();
    for (int e = t; e < 512; e += 256) {
        int i = e >> 6, d = e & 63;
        int pair = i >> 1, comp = i & 1, half = d >> 5, d8 = (d & 31) >> 2, elem = d & 3;
        int c = comp * 2 + half;
        float A = 0.f;
        #pragma unroll
        for (int jg = 0; jg < 8; ++jg) {
            int tp = jg * 32 + pair * 8 + d8;
            A += sm[AQ_RED + tp * 16 + c * 4 + elem];
        }
        g_pA[((b * NCH + chunk) * 8 + i) * 64 + d] = A;
    }
    if (t < 8) {
        float w = 0.f, ti = 0.f;
        #pragma unroll 8
        for (int jj = 0; jj < 64; ++jj) { w += sm[AQ_WR + jj * 8 + t]; ti += sm[AQ_TR + jj * 8 + t]; }
        g_pW[(b * NCH + chunk) * 8 + t] = w;
        g_pT[(b * NCH + chunk) * 8 + t] = ti;
    }
}

// =======================================================================
// INIT: 256 blocks (batch) x 256 threads
// =======================================================================
__global__ __launch_bounds__(256) void init_kernel(
    const float* __restrict__ slots_in, const float* __restrict__ prior_slots,
    const float* __restrict__ eps_noise,
    const float* __restrict__ ni_g, const float* __restrict__ ni_b,
    const float* __restrict__ sr_W1, const float* __restrict__ sr_b1,
    const float* __restrict__ sr_W2, const float* __restrict__ sr_b2,
    const float* __restrict__ pr_W1, const float* __restrict__ pr_b1,
    const float* __restrict__ pr_W2, const float* __restrict__ pr_b2,
    const float* __restrict__ Wq, const float* __restrict__ bq,
    const float* __restrict__ Wk, const float* __restrict__ bk)
{
    __shared__ float P0[512], S0[512], B1[1024], B2[1024], SLN[512], QT[512];
    __shared__ float RD1[256], RD2[256];
    const int b = blockIdx.x, t = threadIdx.x;
    const int tt = t & 63, r2 = (t >> 6) * 2;     // 64-out phases: 2 rows
    const int m = t & 127, i4 = (t >> 7) * 4;     // 128-out phases: 4 rows

    for (int e = t; e < 512; e += 256) {
        P0[e] = prior_slots[(long)b * 512 + e];
        S0[e] = slots_in[(long)b * 512 + e];
    }
    if (t < 8) g_kl[b * 8 + t] = 0.f;
    __syncthreads();
    {
        float acc[4] = {0,0,0,0};
        const float4* w4 = (const float4*)(pr_W1 + m * 64);
        const float4* p4 = (const float4*)P0;
        #pragma unroll 4
        for (int k = 0; k < 16; ++k) {
            float4 w = __ldg(w4 + k);
            #pragma unroll
            for (int i = 0; i < 4; ++i) acc[i] += dot4(w, p4[(i4 + i) * 16 + k]);
        }
        float b1 = __ldg(pr_b1 + m);
        #pragma unroll
        for (int i = 0; i < 4; ++i) B1[(i4 + i) * 128 + m] = fmaxf(acc[i] + b1, 0.f);
    }
    __syncthreads();
    {
        float acc[4] = {0,0,0,0};
        const float4* w4 = (const float4*)(pr_W2 + m * 128);
        const float4* h4 = (const float4*)B1;
        #pragma unroll 4
        for (int k = 0; k < 32; ++k) {
            float4 w = __ldg(w4 + k);
            #pragma unroll
            for (int i = 0; i < 4; ++i) acc[i] += dot4(w, h4[(i4 + i) * 32 + k]);
        }
        float b2 = __ldg(pr_b2 + m);
        #pragma unroll
        for (int i = 0; i < 4; ++i) g_prior[(long)b * 1024 + (i4 + i) * 128 + m] = acc[i] + b2;
    }
    __syncthreads();
    {
        float acc[4] = {0,0,0,0};
        const float4* w4 = (const float4*)(sr_W1 + m * 64);
        const float4* s4 = (const float4*)S0;
        #pragma unroll 4
        for (int k = 0; k < 16; ++k) {
            float4 w = __ldg(w4 + k);
            #pragma unroll
            for (int i = 0; i < 4; ++i) acc[i] += dot4(w, s4[(i4 + i) * 16 + k]);
        }
        float b1 = __ldg(sr_b1 + m);
        #pragma unroll
        for (int i = 0; i < 4; ++i) B1[(i4 + i) * 128 + m] = fmaxf(acc[i] + b1, 0.f);
    }
    __syncthreads();
    {
        float acc[4] = {0,0,0,0};
        const float4* w4 = (const float4*)(sr_W2 + m * 128);
        const float4* h4 = (const float4*)B1;
        #pragma unroll 4
        for (int k = 0; k < 32; ++k) {
            float4 w = __ldg(w4 + k);
            #pragma unroll
            for (int i = 0; i < 4; ++i) acc[i] += dot4(w, h4[(i4 + i) * 32 + k]);
        }
        float b2 = __ldg(sr_b2 + m);
        #pragma unroll
        for (int i = 0; i < 4; ++i) B2[(i4 + i) * 128 + m] = acc[i] + b2;
    }
    __syncthreads();
    for (int e = t; e < 512; e += 256) {
        int i = e >> 6, d = e & 63;
        float mu = B2[i * 128 + d], lv = B2[i * 128 + 64 + d];
        float v = eps_noise[(long)b * 512 + e] * expf(0.5f * lv) + mu;
        SLN[e] = v;
        g_slots[(long)b * 512 + e] = v;
    }
    __syncthreads();
    {
        float acc[2] = {0,0};
        const float4* w4 = (const float4*)(Wq + tt * 64);
        const float4* s4 = (const float4*)SLN;
        #pragma unroll 4
        for (int k = 0; k < 16; ++k) {
            float4 w = __ldg(w4 + k);
            #pragma unroll
            for (int r = 0; r < 2; ++r) acc[r] += dot4(w, s4[(r2 + r) * 16 + k]);
        }
        float bb = __ldg(bq + tt);
        #pragma unroll
        for (int r = 0; r < 2; ++r) QT[(r2 + r) * 64 + tt] = acc[r] + bb;
    }
    __syncthreads();
    {
        float qp[2] = {0,0};
        for (int o = 0; o < 64; ++o) {
            float w = __ldg(Wk + o * 64 + tt);
            #pragma unroll
            for (int r = 0; r < 2; ++r) qp[r] += QT[(r2 + r) * 64 + o] * w;
        }
        float gg = ni_g[tt], nb = ni_b[tt], bkt = bk[tt];
        #pragma unroll
        for (int r = 0; r < 2; ++r) {
            int i = r2 + r;
            float q = qp[r] * SCALEF;
            float qgv = q * gg;
            g_qg[(long)b * 512 + i * 64 + tt] = qgv;
            B1[i * 64 + tt] = qgv;
            B1[512 + i * 64 + tt] = q * nb + SCALEF * QT[i * 64 + tt] * bkt;
        }
    }
    __syncthreads();
    {
        int ir = t >> 5, d0 = t & 31;
        float s1 = B1[ir * 64 + d0] + B1[ir * 64 + d0 + 32];
        float s2 = B1[512 + ir * 64 + d0] + B1[512 + ir * 64 + d0 + 32];
        RD1[t] = s1; RD2[t] = s2;
    }
    __syncthreads();
    if (t < 8) {
        float s1 = 0.f, s2 = 0.f;
        #pragma unroll
        for (int q = 0; q < 32; ++q) { s1 += RD1[t * 32 + q]; s2 += RD2[t * 32 + q]; }
        g_qgs[b * 8 + t] = s1;
        g_qb[b * 8 + t]  = s2;
    }
}

// =======================================================================
// UPDATE: 256 blocks (batch) x 256 threads
// =======================================================================
__global__ __launch_bounds__(256) void update_kernel(
    const float* __restrict__ Wv, const float* __restrict__ bv,
    const float* __restrict__ gru_Wih, const float* __restrict__ gru_Whh,
    const float* __restrict__ gru_bih, const float* __restrict__ gru_bhh,
    const float* __restrict__ npf_g, const float* __restrict__ npf_b,
    const float* __restrict__ mlp_W1, const float* __restrict__ mlp_b1,
    const float* __restrict__ mlp_W2, const float* __restrict__ mlp_b2,
    const float* __restrict__ sr_W1, const float* __restrict__ sr_b1,
    const float* __restrict__ sr_W2, const float* __restrict__ sr_b2,
    const float* __restrict__ ni_g, const float* __restrict__ ni_b,
    const float* __restrict__ Wq, const float* __restrict__ bq,
    const float* __restrict__ Wk, const float* __restrict__ bk,
    int final_iter, float* __restrict__ out)
{
    __shared__ float SL[512], NUM[512], U[512], HN[512], LNX[512], SLN[512], QT[512];
    __shared__ float B1[1024], B2[1024];
    __shared__ float RD1[256], RD2[256], MM[8], RS[8], DINV[8], TI[8];
    const int b = blockIdx.x, t = threadIdx.x;
    const int tt = t & 63, r2 = (t >> 6) * 2;
    const int m = t & 127, i4 = (t >> 7) * 4;

    for (int e = t; e < 512; e += 256) SL[e] = g_slots[(long)b * 512 + e];
    if (t < 8) {
        float den = 0.f, ti = 0.f;
        #pragma unroll
        for (int c = 0; c < NCH; ++c) {
            den += g_pW[(b * NCH + c) * 8 + t];
            ti  += g_pT[(b * NCH + c) * 8 + t];
        }
        DINV[t] = 1.0f / den; TI[t] = ti;
    }
    __syncthreads();
    {
        float gg = ni_g[tt], bb = ni_b[tt];
        #pragma unroll
        for (int r = 0; r < 2; ++r) {
            int i = r2 + r;
            float A = 0.f;
            #pragma unroll
            for (int c = 0; c < NCH; ++c) A += g_pA[((b * NCH + c) * 8 + i) * 64 + tt];
            NUM[i * 64 + tt] = gg * (A - TI[i]) * DINV[i] + bb;
        }
    }
    __syncthreads();
    {
        float acc[2] = {0,0};
        const float4* w4 = (const float4*)(Wv + tt * 64);
        const float4* n4 = (const float4*)NUM;
        #pragma unroll 4
        for (int k = 0; k < 16; ++k) {
            float4 w = __ldg(w4 + k);
            #pragma unroll
            for (int r = 0; r < 2; ++r) acc[r] += dot4(w, n4[(r2 + r) * 16 + k]);
        }
        float bb = __ldg(bv + tt);
        #pragma unroll
        for (int r = 0; r < 2; ++r) U[(r2 + r) * 64 + tt] = acc[r] + bb;
    }
    __syncthreads();
    {
        const float4* u4 = (const float4*)U;
        const float4* s4 = (const float4*)SL;
        float rr[2], zz[2], nn[2];
        {
            float ai[2] = {0,0}, ah[2] = {0,0};
            const float4* wi = (const float4*)(gru_Wih + tt * 64);
            const float4* wh = (const float4*)(gru_Whh + tt * 64);
            #pragma unroll 4
            for (int k = 0; k < 16; ++k) {
                float4 a = __ldg(wi + k), h = __ldg(wh + k);
                #pragma unroll
                for (int r = 0; r < 2; ++r) {
                    ai[r] += dot4(a, u4[(r2 + r) * 16 + k]);
                    ah[r] += dot4(h, s4[(r2 + r) * 16 + k]);
                }
            }
            float bi = __ldg(gru_bih + tt), bh = __ldg(gru_bhh + tt);
            #pragma unroll
            for (int r = 0; r < 2; ++r) rr[r] = sigmoidf_(ai[r] + bi + ah[r] + bh);
        }
        {
            float ai[2] = {0,0}, ah[2] = {0,0};
            const float4* wi = (const float4*)(gru_Wih + (64 + tt) * 64);
            const float4* wh = (const float4*)(gru_Whh + (64 + tt) * 64);
            #pragma unroll 4
            for (int k = 0; k < 16; ++k) {
                float4 a = __ldg(wi + k), h = __ldg(wh + k);
                #pragma unroll
                for (int r = 0; r < 2; ++r) {
                    ai[r] += dot4(a, u4[(r2 + r) * 16 + k]);
                    ah[r] += dot4(h, s4[(r2 + r) * 16 + k]);
                }
            }
            float bi = __ldg(gru_bih + 64 + tt), bh = __ldg(gru_bhh + 64 + tt);
            #pragma unroll
            for (int r = 0; r < 2; ++r) zz[r] = sigmoidf_(ai[r] + bi + ah[r] + bh);
        }
        {
            float ai[2] = {0,0}, ah[2] = {0,0};
            const float4* wi = (const float4*)(gru_Wih + (128 + tt) * 64);
            const float4* wh = (const float4*)(gru_Whh + (128 + tt) * 64);
            #pragma unroll 4
            for (int k = 0; k < 16; ++k) {
                float4 a = __ldg(wi + k), h = __ldg(wh + k);
                #pragma unroll
                for (int r = 0; r < 2; ++r) {
                    ai[r] += dot4(a, u4[(r2 + r) * 16 + k]);
                    ah[r] += dot4(h, s4[(r2 + r) * 16 + k]);
                }
            }
            float bi = __ldg(gru_bih + 128 + tt), bh = __ldg(gru_bhh + 128 + tt);
            #pragma unroll
            for (int r = 0; r < 2; ++r) nn[r] = tanhf(ai[r] + bi + rr[r] * (ah[r] + bh));
        }
        #pragma unroll
        for (int r = 0; r < 2; ++r) {
            int i = r2 + r;
            HN[i * 64 + tt] = (1.f - zz[r]) * nn[r] + zz[r] * SL[i * 64 + tt];
        }
    }
    __syncthreads();
    {
        int ir = t >> 5, d0 = t & 31;
        float v0 = HN[ir * 64 + d0], v1 = HN[ir * 64 + d0 + 32];
        RD1[t] = v0 + v1; RD2[t] = v0 * v0 + v1 * v1;
    }
    __syncthreads();
    if (t < 8) {
        float s1 = 0.f, s2 = 0.f;
        #pragma unroll
        for (int q = 0; q < 32; ++q) { s1 += RD1[t * 32 + q]; s2 += RD2[t * 32 + q]; }
        float mu = s1 * (1.f / 64.f);
        float var = s2 * (1.f / 64.f) - mu * mu;
        MM[t] = mu; RS[t] = rsqrtf(var + 1e-5f);
    }
    __syncthreads();
    {
        float gg = npf_g[tt], bb = npf_b[tt];
        #pragma unroll
        for (int r = 0; r < 2; ++r) {
            int i = r2 + r;
            LNX[i * 64 + tt] = (HN[i * 64 + tt] - MM[i]) * RS[i] * gg + bb;
        }
    }
    __syncthreads();
    {
        float acc[4] = {0,0,0,0};
        const float4* w4 = (const float4*)(mlp_W1 + m * 64);
        const float4* l4 = (const float4*)LNX;
        #pragma unroll 4
        for (int k = 0; k < 16; ++k) {
            float4 w = __ldg(w4 + k);
            #pragma unroll
            for (int i = 0; i < 4; ++i) acc[i] += dot4(w, l4[(i4 + i) * 16 + k]);
        }
        float b1 = __ldg(mlp_b1 + m);
        #pragma unroll
        for (int i = 0; i < 4; ++i) B1[(i4 + i) * 128 + m] = fmaxf(acc[i] + b1, 0.f);
    }
    __syncthreads();
    {
        float acc[2] = {0,0};
        const float4* w4 = (const float4*)(mlp_W2 + tt * 128);
        const float4* h4 = (const float4*)B1;
        #pragma unroll 4
        for (int k = 0; k < 32; ++k) {
            float4 w = __ldg(w4 + k);
            #pragma unroll
            for (int r = 0; r < 2; ++r) acc[r] += dot4(w, h4[(r2 + r) * 32 + k]);
        }
        float bb = __ldg(mlp_b2 + tt);
        #pragma unroll
        for (int r = 0; r < 2; ++r) {
            int i = r2 + r;
            float v = HN[i * 64 + tt] + acc[r] + bb;
            SLN[i * 64 + tt] = v;
            g_slots[(long)b * 512 + i * 64 + tt] = v;
            if (final_iter) out[(long)b * 512 + i * 64 + tt] = v;
        }
    }
    __syncthreads();
    {
        float acc[4] = {0,0,0,0};
        const float4* w4 = (const float4*)(sr_W1 + m * 64);
        const float4* s4 = (const float4*)SLN;
        #pragma unroll 4
        for (int k = 0; k < 16; ++k) {
            float4 w = __ldg(w4 + k);
            #pragma unroll
            for (int i = 0; i < 4; ++i) acc[i] += dot4(w, s4[(i4 + i) * 16 + k]);
        }
        float b1 = __ldg(sr_b1 + m);
        #pragma unroll
        for (int i = 0; i < 4; ++i) B1[(i4 + i) * 128 + m] = fmaxf(acc[i] + b1, 0.f);
    }
    __syncthreads();
    {
        float acc[4] = {0,0,0,0};
        const float4* w4 = (const float4*)(sr_W2 + m * 128);
        const float4* h4 = (const float4*)B1;
        #pragma unroll 4
        for (int k = 0; k < 32; ++k) {
            float4 w = __ldg(w4 + k);
            #pragma unroll
            for (int i = 0; i < 4; ++i) acc[i] += dot4(w, h4[(i4 + i) * 32 + k]);
        }
        float b2 = __ldg(sr_b2 + m);
        #pragma unroll
        for (int i = 0; i < 4; ++i) B2[(i4 + i) * 128 + m] = acc[i] + b2;
    }
    __syncthreads();
    if (t < 64) {
        #pragma unroll
        for (int i = 0; i < 8; ++i) {
            float po_m  = B2[i * 128 + t], po_lv = B2[i * 128 + 64 + t];
            float m_pr  = g_prior[(long)b * 1024 + i * 128 + t];
            float lv_pr = g_prior[(long)b * 1024 + i * 128 + 64 + t];
            float dm = po_m - m_pr;
            U[i * 64 + t] = lv_pr - po_lv + (expf(po_lv) + dm * dm) * expf(-lv_pr) - 1.0f;
        }
    }
    __syncthreads();
    {
        int ir = t >> 5, d0 = t & 31;
        RD1[t] = U[ir * 64 + d0] + U[ir * 64 + d0 + 32];
    }
    __syncthreads();
    if (t < 8) {
        float s = 0.f;
        #pragma unroll
        for (int q = 0; q < 32; ++q) s += RD1[t * 32 + q];
        float v = g_kl[b * 8 + t] + 0.5f * s;
        g_kl[b * 8 + t] = v;
        if (final_iter) out[131072 + b * 8 + t] = v;
    }
    if (!final_iter) {
        __syncthreads();
        {
            float acc[2] = {0,0};
            const float4* w4 = (const float4*)(Wq + tt * 64);
            const float4* s4 = (const float4*)SLN;
            #pragma unroll 4
            for (int k = 0; k < 16; ++k) {
                float4 w = __ldg(w4 + k);
                #pragma unroll
                for (int r = 0; r < 2; ++r) acc[r] += dot4(w, s4[(r2 + r) * 16 + k]);
            }
            float bb = __ldg(bq + tt);
            #pragma unroll
            for (int r = 0; r < 2; ++r) QT[(r2 + r) * 64 + tt] = acc[r] + bb;
        }
        __syncthreads();
        {
            float qp[2] = {0,0};
            for (int o = 0; o < 64; ++o) {
                float w = __ldg(Wk + o * 64 + tt);
                #pragma unroll
                for (int r = 0; r < 2; ++r) qp[r] += QT[(r2 + r) * 64 + o] * w;
            }
            float gg = ni_g[tt], nb = ni_b[tt], bkt = bk[tt];
            #pragma unroll
            for (int r = 0; r < 2; ++r) {
                int i = r2 + r;
                float q = qp[r] * SCALEF;
                float qgv = q * gg;
                g_qg[(long)b * 512 + i * 64 + tt] = qgv;
                B1[i * 64 + tt] = qgv;
                B1[512 + i * 64 + tt] = q * nb + SCALEF * QT[i * 64 + tt] * bkt;
            }
        }
        __syncthreads();
        {
            int ir = t >> 5, d0 = t & 31;
            RD1[t] = B1[ir * 64 + d0] + B1[ir * 64 + d0 + 32];
            RD2[t] = B1[512 + ir * 64 + d0] + B1[512 + ir * 64 + d0 + 32];
        }
        __syncthreads();
        if (t < 8) {
            float s1 = 0.f, s2 = 0.f;
            #pragma unroll
            for (int q = 0; q < 32; ++q) { s1 += RD1[t * 32 + q]; s2 += RD2[t * 32 + q]; }
            g_qgs[b * 8 + t] = s1;
            g_qb[b * 8 + t]  = s2;
        }
    }
}

// =======================================================================
extern "C" void kernel_launch(void* const* d_in, const int* in_sizes, int n_in,
                              void* d_out, int out_size)
{
    const float* inputs      = (const float*)d_in[0];
    const float* slots       = (const float*)d_in[1];
    const float* prior_slots = (const float*)d_in[2];
    const float* eps_noise   = (const float*)d_in[3];
    const float* ni_g  = (const float*)d_in[4];
    const float* ni_b  = (const float*)d_in[5];
    const float* npf_g = (const float*)d_in[6];
    const float* npf_b = (const float*)d_in[7];
    const float* Wq = (const float*)d_in[8];
    const float* bq = (const float*)d_in[9];
    const float* Wk = (const float*)d_in[10];
    const float* bk = (const float*)d_in[11];
    const float* Wv = (const float*)d_in[12];
    const float* bv = (const float*)d_in[13];
    const float* sr_W1 = (const float*)d_in[14];
    const float* sr_b1 = (const float*)d_in[15];
    const float* sr_W2 = (const float*)d_in[16];
    const float* sr_b2 = (const float*)d_in[17];
    const float* pr_W1 = (const float*)d_in[18];
    const float* pr_b1 = (const float*)d_in[19];
    const float* pr_W2 = (const float*)d_in[20];
    const float* pr_b2 = (const float*)d_in[21];
    const float* gru_Wih = (const float*)d_in[22];
    const float* gru_Whh = (const float*)d_in[23];
    const float* gru_bih = (const float*)d_in[24];
    const float* gru_bhh = (const float*)d_in[25];
    const float* mlp_W1 = (const float*)d_in[26];
    const float* mlp_b1 = (const float*)d_in[27];
    const float* mlp_W2 = (const float*)d_in[28];
    const float* mlp_b2 = (const float*)d_in[29];

    cudaFuncSetAttribute(attn_kernel, cudaFuncAttributeMaxDynamicSharedMemorySize, AQ_BYTES);

    init_kernel<<<NBATCH, 256>>>(slots, prior_slots, eps_noise,
                                 ni_g, ni_b,
                                 sr_W1, sr_b1, sr_W2, sr_b2,
                                 pr_W1, pr_b1, pr_W2, pr_b2,
                                 Wq, bq, Wk, bk);
    for (int it = 0; it < 3; ++it) {
        attn_kernel<<<NBATCH * NCH, 256, AQ_BYTES>>>(inputs);
        update_kernel<<<NBATCH, 256>>>(Wv, bv,
                                       gru_Wih, gru_Whh, gru_bih, gru_bhh,
                                       npf_g, npf_b,
                                       mlp_W1, mlp_b1, mlp_W2, mlp_b2,
                                       sr_W1, sr_b1, sr_W2, sr_b2,
                                       ni_g, ni_b, Wq, bq, Wk, bk,
                                       it == 2 ? 1 : 0, (float*)d_out);
    }
}